// round 2
// baseline (speedup 1.0000x reference)
#include <cuda_runtime.h>
#include <math.h>

// Problem shape (fixed by the reference setup_inputs)
#define NS 5        // S: num support classes
#define NQ 512      // Q: num queries
#define NT 64       // T: tokens pooled (mean)
#define ND 2048     // D: feature dim
#define ND4 (ND/4)  // 512 float4 per row
#define EPS 1e-8f

// Scratch (no allocations allowed in kernel_launch)
__device__ float g_sp[NS * ND];   // pooled support [S, D]
__device__ float g_sn[NS];        // support norms
__device__ float g_dist[NQ * NS]; // cosine sim [Q, S]

__device__ __forceinline__ float4 f4add(float4 a, float4 b) {
    a.x += b.x; a.y += b.y; a.z += b.z; a.w += b.w; return a;
}
__device__ __forceinline__ float4 f4scale(float4 a, float s) {
    a.x *= s; a.y *= s; a.z *= s; a.w *= s; return a;
}
__device__ __forceinline__ float f4dot(float4 a, float4 b) {
    return a.x * b.x + a.y * b.y + a.z * b.z + a.w * b.w;
}
__device__ __forceinline__ float warp_sum(float v) {
    #pragma unroll
    for (int o = 16; o > 0; o >>= 1) v += __shfl_xor_sync(0xffffffffu, v, o);
    return v;
}

// Kernel 1: pool supp over T -> g_sp, and norms -> g_sn.  grid=(NS), block=256
__global__ void pool_supp_kernel(const float* __restrict__ supp) {
    const int s = blockIdx.x;
    const int tid = threadIdx.x;
    const float4* base = reinterpret_cast<const float4*>(supp + (size_t)s * NT * ND);

    float4 acc0 = make_float4(0.f, 0.f, 0.f, 0.f);
    float4 acc1 = make_float4(0.f, 0.f, 0.f, 0.f);
    #pragma unroll 8
    for (int t = 0; t < NT; t++) {
        const float4* row = base + (size_t)t * ND4;
        acc0 = f4add(acc0, row[tid]);
        acc1 = f4add(acc1, row[tid + 256]);
    }
    const float inv = 1.0f / (float)NT;
    acc0 = f4scale(acc0, inv);
    acc1 = f4scale(acc1, inv);

    float4* sp4 = reinterpret_cast<float4*>(g_sp + (size_t)s * ND);
    sp4[tid] = acc0;
    sp4[tid + 256] = acc1;

    // norm^2 partial
    float p = f4dot(acc0, acc0) + f4dot(acc1, acc1);
    p = warp_sum(p);
    __shared__ float red[8];
    if ((tid & 31) == 0) red[tid >> 5] = p;
    __syncthreads();
    if (tid == 0) {
        float tot = 0.f;
        #pragma unroll
        for (int w = 0; w < 8; w++) tot += red[w];
        g_sn[s] = sqrtf(tot);
    }
}

// Kernel 2: per-query pooling + cosine sim.  grid=(NQ), block=256
// out_dist points at the (1-dist) region of d_out.
__global__ void query_dist_kernel(const float* __restrict__ query,
                                  float* __restrict__ out_dist) {
    __shared__ float red[8][6];

    const int q = blockIdx.x;
    const int tid = threadIdx.x;
    const int wid = tid >> 5;

    // Stream-pool this query's [T, D] slab (512 KB) — the HBM-bound part
    const float4* base = reinterpret_cast<const float4*>(query + (size_t)q * NT * ND);
    float4 acc0 = make_float4(0.f, 0.f, 0.f, 0.f);
    float4 acc1 = make_float4(0.f, 0.f, 0.f, 0.f);
    #pragma unroll 8
    for (int t = 0; t < NT; t++) {
        const float4* row = base + (size_t)t * ND4;
        acc0 = f4add(acc0, row[tid]);
        acc1 = f4add(acc1, row[tid + 256]);
    }
    const float inv = 1.0f / (float)NT;
    acc0 = f4scale(acc0, inv);
    acc1 = f4scale(acc1, inv);

    // 6 partial reductions: 5 dot(qp, sp) + ||qp||^2.
    // g_sp is 40 KB total -> L2-resident; each thread reads 6x32B via L2.
    const float4* sp_g = reinterpret_cast<const float4*>(g_sp);
    float part[6];
    part[5] = f4dot(acc0, acc0) + f4dot(acc1, acc1);
    #pragma unroll
    for (int s = 0; s < NS; s++) {
        part[s] = f4dot(acc0, __ldg(&sp_g[s * ND4 + tid])) +
                  f4dot(acc1, __ldg(&sp_g[s * ND4 + tid + 256]));
    }
    #pragma unroll
    for (int j = 0; j < 6; j++) {
        float v = warp_sum(part[j]);
        if ((tid & 31) == 0) red[wid][j] = v;
    }
    __syncthreads();

    if (tid == 0) {
        float tot[6];
        #pragma unroll
        for (int j = 0; j < 6; j++) {
            float t2 = 0.f;
            #pragma unroll
            for (int w = 0; w < 8; w++) t2 += red[w][j];
            tot[j] = t2;
        }
        const float qn = sqrtf(tot[5]);
        #pragma unroll
        for (int s = 0; s < NS; s++) {
            float denom = fmaxf(qn * __ldg(&g_sn[s]), EPS);
            float d = tot[s] / denom;
            g_dist[q * NS + s] = d;
            out_dist[q * NS + s] = 1.0f - d;
        }
    }
}

// Kernel 3: cross-entropy loss.  grid=1, block=NQ (512)
// write_loss: whether d_out has a loss slot at index 0.
__global__ void loss_kernel(const int* __restrict__ ys32,
                            float* __restrict__ out, int write_loss) {
    __shared__ int s_is64;
    __shared__ float red[16];
    const int tid = threadIdx.x;

    if (tid == 0) {
        // Detect int64 vs int32 labels. Values are in [0,5). For int64 (LE),
        // odd 32-bit words are the (zero) high halves of the first 256 entries.
        // Reading 512 int32 words is in-bounds for both layouts.
        int f = 1;
        for (int i = 1; i < NQ; i += 2) {
            if (ys32[i] != 0) { f = 0; break; }
        }
        s_is64 = f;
    }
    __syncthreads();

    const int y = s_is64 ? ys32[2 * tid] : ys32[tid];

    float d[NS];
    #pragma unroll
    for (int s = 0; s < NS; s++) d[s] = g_dist[tid * NS + s];
    float m = d[0];
    #pragma unroll
    for (int s = 1; s < NS; s++) m = fmaxf(m, d[s]);
    float se = 0.f;
    #pragma unroll
    for (int s = 0; s < NS; s++) se += __expf(d[s] - m);
    const float lse = m + logf(se);
    float nlp = -(d[y] - lse);

    nlp = warp_sum(nlp);
    if ((tid & 31) == 0) red[tid >> 5] = nlp;
    __syncthreads();
    if (tid == 0 && write_loss) {
        float tot = 0.f;
        #pragma unroll
        for (int w = 0; w < 16; w++) tot += red[w];
        out[0] = tot * (1.0f / (float)NQ);
    }
}

extern "C" void kernel_launch(void* const* d_in, const int* in_sizes, int n_in,
                              void* d_out, int out_size) {
    const float* supp  = (const float*)d_in[0];
    const float* query = (const float*)d_in[1];
    const int*   ys    = (const int*)d_in[2];
    // Defensive: supp has 655,360 elems, query 67,108,864 — swap if reordered.
    if (n_in >= 2 && in_sizes[0] > in_sizes[1]) {
        const float* t = supp; supp = query; query = t;
    }
    float* out = (float*)d_out;

    // Tuple flattening: expect out_size = 1 + Q*S (loss first, then 1-dist).
    // If the harness exposes only Q*S elements, write dist at offset 0.
    const int dist_off = (out_size > NQ * NS) ? (out_size - NQ * NS) : 0;
    const int write_loss = (out_size > NQ * NS) ? 1 : 0;

    pool_supp_kernel<<<NS, 256>>>(supp);
    query_dist_kernel<<<NQ, 256>>>(query, out + dist_off);
    loss_kernel<<<1, NQ>>>(ys, out, write_loss);
}

// round 4
// speedup vs baseline: 1.2153x; 1.2153x over previous
#include <cuda_runtime.h>
#include <math.h>

// Problem shape (fixed by the reference setup_inputs)
#define NS 5        // S: num support classes
#define NQ 512      // Q: num queries
#define NT 64       // T: tokens pooled (mean)
#define NTH (NT/2)  // half split for pooling
#define ND 2048     // D: feature dim
#define ND4 (ND/4)  // 512 float4 per row
#define EPS 1e-8f

// Scratch (no allocations allowed in kernel_launch)
__device__ float g_sph[2][NS * ND];    // per-half raw support sums [2][S, D]
__device__ float g_qph[2][NQ * ND];    // per-half raw query sums   [2][Q, D]
__device__ float g_dist[NQ * NS];      // cosine sim [Q, S]

__device__ __forceinline__ float4 f4add(float4 a, float4 b) {
    a.x += b.x; a.y += b.y; a.z += b.z; a.w += b.w; return a;
}
__device__ __forceinline__ float4 f4scale(float4 a, float s) {
    a.x *= s; a.y *= s; a.z *= s; a.w *= s; return a;
}
__device__ __forceinline__ float f4dot(float4 a, float4 b) {
    return a.x * b.x + a.y * b.y + a.z * b.z + a.w * b.w;
}
__device__ __forceinline__ float warp_sum(float v) {
    #pragma unroll
    for (int o = 16; o > 0; o >>= 1) v += __shfl_xor_sync(0xffffffffu, v, o);
    return v;
}

// ─── Kernel A: ONE uniform streaming pass over supp AND query ──────────────
// grid = 2*NS + 2*NQ = 1034 blocks, block = 256. Every CTA pools exactly
// 32 rows x 2048 floats (256 KB) of raw sums -> single balanced wave.
//   bid < 2*NS : supp row (bid>>1), half (bid&1) -> g_sph
//   else       : query row q, half              -> g_qph
__global__ void __launch_bounds__(256, 8)
pool_all_kernel(const float* __restrict__ supp,
                const float* __restrict__ query) {
    const int bid = blockIdx.x;
    const int tid = threadIdx.x;

    const float* src;
    float* dst;
    if (bid < 2 * NS) {
        const int s = bid >> 1, half = bid & 1;
        src = supp + ((size_t)s * NT + (size_t)half * NTH) * ND;
        dst = &g_sph[half][(size_t)s * ND];
    } else {
        const int i = bid - 2 * NS;
        const int q = i >> 1, half = i & 1;
        src = query + ((size_t)q * NT + (size_t)half * NTH) * ND;
        dst = &g_qph[half][(size_t)q * ND];
    }

    const float4* base = reinterpret_cast<const float4*>(src);
    float4 acc0 = make_float4(0.f, 0.f, 0.f, 0.f);
    float4 acc1 = make_float4(0.f, 0.f, 0.f, 0.f);
    #pragma unroll 8
    for (int t = 0; t < NTH; t++) {
        const float4* row = base + (size_t)t * ND4;
        acc0 = f4add(acc0, row[tid]);
        acc1 = f4add(acc1, row[tid + 256]);
    }
    float4* d4 = reinterpret_cast<float4*>(dst);
    d4[tid] = acc0;          // raw sums; scaled in kernel B
    d4[tid + 256] = acc1;
}

// ─── Kernel B: combine halves + cosine sim ─────────────────────────────────
// grid = NQ, block = 256. All reads are L2-resident (8.1 MB scratch).
// 11 block reductions: 5 dot(q,s), 5 ||s||^2 (redundant per block, cheap),
// 1 ||q||^2.
__global__ void __launch_bounds__(256, 8)
dist_kernel(float* __restrict__ out_dist) {
    __shared__ float red[8][11];
    const int q = blockIdx.x;
    const int tid = threadIdx.x;
    const int wid = tid >> 5;
    const float inv = 1.0f / (float)NT;

    const float4* h0 = reinterpret_cast<const float4*>(&g_qph[0][(size_t)q * ND]);
    const float4* h1 = reinterpret_cast<const float4*>(&g_qph[1][(size_t)q * ND]);
    float4 acc0 = f4scale(f4add(h0[tid], h1[tid]), inv);
    float4 acc1 = f4scale(f4add(h0[tid + 256], h1[tid + 256]), inv);

    float part[11];
    part[10] = f4dot(acc0, acc0) + f4dot(acc1, acc1);
    #pragma unroll
    for (int s = 0; s < NS; s++) {
        const float4* s0 = reinterpret_cast<const float4*>(&g_sph[0][(size_t)s * ND]);
        const float4* s1 = reinterpret_cast<const float4*>(&g_sph[1][(size_t)s * ND]);
        float4 sp0 = f4scale(f4add(__ldg(&s0[tid]),       __ldg(&s1[tid])),       inv);
        float4 sp1 = f4scale(f4add(__ldg(&s0[tid + 256]), __ldg(&s1[tid + 256])), inv);
        part[s]      = f4dot(acc0, sp0) + f4dot(acc1, sp1);
        part[5 + s]  = f4dot(sp0, sp0) + f4dot(sp1, sp1);
    }
    #pragma unroll
    for (int j = 0; j < 11; j++) {
        float v = warp_sum(part[j]);
        if ((tid & 31) == 0) red[wid][j] = v;
    }
    __syncthreads();

    if (tid == 0) {
        float tot[11];
        #pragma unroll
        for (int j = 0; j < 11; j++) {
            float t2 = 0.f;
            #pragma unroll
            for (int w = 0; w < 8; w++) t2 += red[w][j];
            tot[j] = t2;
        }
        const float qn = sqrtf(tot[10]);
        #pragma unroll
        for (int s = 0; s < NS; s++) {
            float denom = fmaxf(qn * sqrtf(tot[5 + s]), EPS);
            float d = tot[s] / denom;
            g_dist[q * NS + s] = d;
            out_dist[q * NS + s] = 1.0f - d;
        }
    }
}

// ─── Kernel C: cross-entropy loss ──────────────────────────────────────────
__global__ void loss_kernel(const int* __restrict__ ys32,
                            float* __restrict__ out, int write_loss) {
    __shared__ int s_is64;
    __shared__ float red[16];
    const int tid = threadIdx.x;

    if (tid == 0) {
        // Detect int64 vs int32 labels (values < 5; int64 high words are 0).
        int f = 1;
        for (int i = 1; i < NQ; i += 2) {
            if (ys32[i] != 0) { f = 0; break; }
        }
        s_is64 = f;
    }
    __syncthreads();

    const int y = s_is64 ? ys32[2 * tid] : ys32[tid];

    float d[NS];
    #pragma unroll
    for (int s = 0; s < NS; s++) d[s] = g_dist[tid * NS + s];
    float m = d[0];
    #pragma unroll
    for (int s = 1; s < NS; s++) m = fmaxf(m, d[s]);
    float se = 0.f;
    #pragma unroll
    for (int s = 0; s < NS; s++) se += __expf(d[s] - m);
    const float lse = m + logf(se);
    float nlp = -(d[y] - lse);

    nlp = warp_sum(nlp);
    if ((tid & 31) == 0) red[tid >> 5] = nlp;
    __syncthreads();
    if (tid == 0 && write_loss) {
        float tot = 0.f;
        #pragma unroll
        for (int w = 0; w < 16; w++) tot += red[w];
        out[0] = tot * (1.0f / (float)NQ);
    }
}

extern "C" void kernel_launch(void* const* d_in, const int* in_sizes, int n_in,
                              void* d_out, int out_size) {
    const float* supp  = (const float*)d_in[0];
    const float* query = (const float*)d_in[1];
    const int*   ys    = (const int*)d_in[2];
    if (n_in >= 2 && in_sizes[0] > in_sizes[1]) {
        const float* t = supp; supp = query; query = t;
    }
    float* out = (float*)d_out;

    const int dist_off = (out_size > NQ * NS) ? (out_size - NQ * NS) : 0;
    const int write_loss = (out_size > NQ * NS) ? 1 : 0;

    pool_all_kernel<<<2 * NS + 2 * NQ, 256>>>(supp, query);
    dist_kernel<<<NQ, 256>>>(out + dist_off);
    loss_kernel<<<1, NQ>>>(ys, out, write_loss);
}